// round 15
// baseline (speedup 1.0000x reference)
#include <cuda_runtime.h>
#include <cuda_bf16.h>
#include <math.h>
#include <stdint.h>

#define N_NODES 50000
#define N_EDGES 800000
#define NG      512
#define D       128
#define TXT     768
#define MAN     14
#define LN_EPS  1e-5f
#define SCAN_BLOCKS 49   // ceil(50000/1024)

// ---------------- scratch (device globals; no allocs allowed) ----------------
__device__ float g_h0 [N_NODES * D];   // layernorm(x)
__device__ float g_agg[N_NODES * D];   // neighbor MEAN
__device__ float g_h1 [N_NODES * D];   // h2 = gelu(LN(GEMM out))
__device__ float g_gate[N_NODES];      // gate logits
__device__ int   g_cnt[N_NODES];       // in-degree histogram (zero-init; self-resetting)
__device__ int   g_off[N_NODES];       // exclusive scan (bucket start)
__device__ int   g_cursor[N_NODES];    // scatter cursor
__device__ int   g_aggv[64];           // scan block sums
__device__ int   g_scan_ctr;           // publish counter (zero-init; reset by edge_sort)
__device__ int   g_ssrc[N_EDGES];      // src sorted by dst
__device__ float g_msg [NG * D];       // precomputed gelu(text@msgW+b)
__device__ float g_feat[NG * D];       // precomputed gelu(feat@featW+b)
// bf16 split planes of [Wl;Wr], TRANSPOSED: [n][k] with k contiguous (256 per n)
__device__ unsigned short g_Bh[D * 2 * D];
__device__ unsigned short g_Bl[D * 2 * D];

__device__ __forceinline__ float gelu_exact(float x) {
    return 0.5f * x * (1.0f + erff(x * 0.70710678118654752440f));
}

__device__ __forceinline__ unsigned short bf16_of(float x) {
    __nv_bfloat16 h = __float2bfloat16_rn(x);
    return *(unsigned short*)&h;
}
__device__ __forceinline__ float bf16_back(unsigned short u) {
    __nv_bfloat16 h = *(__nv_bfloat16*)&u;
    return __bfloat162float(h);
}

#define MMA_BF16(c, a, b)                                                     \
    asm volatile("mma.sync.aligned.m16n8k16.row.col.f32.bf16.bf16.f32 "       \
                 "{%0,%1,%2,%3}, {%4,%5,%6,%7}, {%8,%9}, {%0,%1,%2,%3};"      \
                 : "+f"((c)[0]), "+f"((c)[1]), "+f"((c)[2]), "+f"((c)[3])     \
                 : "r"((a)[0]), "r"((a)[1]), "r"((a)[2]), "r"((a)[3]),        \
                   "r"((b)[0]), "r"((b)[1]))

// ---------------- main K1: h0 = layernorm(x); prep B bf16 planes ----------------
__global__ void k_ln_project(const float* __restrict__ x,
                             const float* __restrict__ w,
                             const float* __restrict__ b,
                             const float* __restrict__ Wl,
                             const float* __restrict__ Wr) {
    int gt = blockIdx.x * blockDim.x + threadIdx.x;
    if (gt < 2 * D * D) {
        int kg = gt >> 7, n = gt & 127;
        float v = (kg < D) ? Wl[(size_t)kg * D + n] : Wr[(size_t)(kg - D) * D + n];
        unsigned short hi = bf16_of(v);
        unsigned short lo = bf16_of(v - bf16_back(hi));
        g_Bh[n * 2 * D + kg] = hi;
        g_Bl[n * 2 * D + kg] = lo;
    }
    int warp = gt >> 5;
    int lane = threadIdx.x & 31;
    if (warp >= N_NODES) return;
    float4 v = ((const float4*)(x + (size_t)warp * D))[lane];
    float s = v.x + v.y + v.z + v.w;
    #pragma unroll
    for (int o = 16; o; o >>= 1) s += __shfl_xor_sync(0xffffffffu, s, o);
    float mu = s * (1.f / 128.f);
    float d0 = v.x - mu, d1 = v.y - mu, d2 = v.z - mu, d3 = v.w - mu;
    float q = d0 * d0 + d1 * d1 + d2 * d2 + d3 * d3;
    #pragma unroll
    for (int o = 16; o; o >>= 1) q += __shfl_xor_sync(0xffffffffu, q, o);
    float rstd = rsqrtf(q * (1.f / 128.f) + LN_EPS);
    float4 wv = ((const float4*)w)[lane];
    float4 bv = ((const float4*)b)[lane];
    float4 o4;
    o4.x = d0 * rstd * wv.x + bv.x;
    o4.y = d1 * rstd * wv.y + bv.y;
    o4.z = d2 * rstd * wv.z + bv.z;
    o4.w = d3 * rstd * wv.w + bv.w;
    ((float4*)(g_h0 + (size_t)warp * D))[lane] = o4;
}

// ---------------- side K2: histogram of dst (g_cnt arrives zeroed) ----------------
__global__ void k_hist(const int* __restrict__ ei) {
    int e = blockIdx.x * blockDim.x + threadIdx.x;
    if (e < N_EDGES) atomicAdd(&g_cnt[ei[N_EDGES + e]], 1);
}

// ---------------- side K3: single-pass scan (publish + spin + warp lookback) ----------------
__global__ void k_scan() {
    __shared__ int s[1024];
    __shared__ int s_prev;
    int t = threadIdx.x, b = blockIdx.x;
    int i = b * 1024 + t;
    int v = (i < N_NODES) ? g_cnt[i] : 0;
    s[t] = v; __syncthreads();
    #pragma unroll
    for (int off = 1; off < 1024; off <<= 1) {
        int a = (t >= off) ? s[t - off] : 0;
        __syncthreads();
        s[t] += a; __syncthreads();
    }
    if (t == 0) {
        g_aggv[b] = s[1023];
        __threadfence();
        atomicAdd(&g_scan_ctr, 1);
        while (atomicAdd(&g_scan_ctr, 0) < SCAN_BLOCKS) { }
    }
    __syncthreads();
    if (t < 32) {
        int v1 = (t < b)      ? *((volatile int*)&g_aggv[t])      : 0;
        int v2 = (t + 32 < b) ? *((volatile int*)&g_aggv[t + 32]) : 0;
        int p = v1 + v2;
        #pragma unroll
        for (int o = 16; o; o >>= 1) p += __shfl_xor_sync(0xffffffffu, p, o);
        if (t == 0) s_prev = p;
    }
    __syncthreads();
    if (i < N_NODES) {
        int o = s[t] - v + s_prev;
        g_off[i] = o;
        g_cursor[i] = o;
    }
}

// ---------------- side K4: scatter src into dst-sorted order; reset scan ctr ----------------
__global__ void k_edge_sort(const int* __restrict__ ei) {
    if (blockIdx.x == 0 && threadIdx.x == 0) g_scan_ctr = 0;   // stream-ordered after k_scan
    int e = blockIdx.x * blockDim.x + threadIdx.x;
    if (e >= N_EDGES) return;
    int src = ei[e];
    int dst = ei[N_EDGES + e];
    int pos = atomicAdd(&g_cursor[dst], 1);
    g_ssrc[pos] = src;
}

// ---------------- main K1b: msg/feat GEMVs ----------------
#define GPG 8
__global__ void __launch_bounds__(128) k_msgfeat(const float* __restrict__ text,
                                                 const float* __restrict__ featm,
                                                 const float* __restrict__ msgW,
                                                 const float* __restrict__ msgb,
                                                 const float* __restrict__ featW,
                                                 const float* __restrict__ featb) {
    __shared__ float ts[GPG][TXT];
    __shared__ float fs[GPG][MAN];
    int g0 = blockIdx.x * GPG, t = threadIdx.x;

    for (int i = t; i < GPG * TXT; i += 128) {
        int q = i / TXT, k = i % TXT;
        ts[q][k] = text[(size_t)(g0 + q) * TXT + k];
    }
    for (int i = t; i < GPG * MAN; i += 128) {
        int q = i / MAN, k = i % MAN;
        fs[q][k] = featm[(size_t)(g0 + q) * MAN + k];
    }
    __syncthreads();

    float accm[GPG];
    #pragma unroll
    for (int q = 0; q < GPG; q++) accm[q] = 0.f;
    #pragma unroll 4
    for (int k = 0; k < TXT; k++) {
        float w = msgW[(size_t)k * D + t];
        #pragma unroll
        for (int q = 0; q < GPG; q++) accm[q] += ts[q][k] * w;
    }
    float mbv = msgb[t];
    #pragma unroll
    for (int q = 0; q < GPG; q++)
        g_msg[(size_t)(g0 + q) * D + t] = gelu_exact(accm[q] + mbv);

    float accf[GPG];
    #pragma unroll
    for (int q = 0; q < GPG; q++) accf[q] = 0.f;
    #pragma unroll
    for (int k = 0; k < MAN; k++) {
        float w = featW[(size_t)k * D + t];
        #pragma unroll
        for (int q = 0; q < GPG; q++) accf[q] += fs[q][k] * w;
    }
    float fbv = featb[t];
    #pragma unroll
    for (int q = 0; q < GPG; q++)
        g_feat[(size_t)(g0 + q) * D + t] = gelu_exact(accf[q] + fbv);
}

// ---------------- side K5: per-node mean aggregation; self-resets g_cnt ----------------
__global__ void __launch_bounds__(256) k_aggregate() {
    int warp = (blockIdx.x * blockDim.x + threadIdx.x) >> 5;
    int lane = threadIdx.x & 31;
    if (warp >= N_NODES) return;
    int start = g_off[warp];
    int cnt   = g_cnt[warp];
    float4 acc = make_float4(0.f, 0.f, 0.f, 0.f);
    for (int j0 = 0; j0 < cnt; j0 += 32) {
        int idx = (j0 + lane < cnt) ? g_ssrc[start + j0 + lane] : 0;
        int nb = min(32, cnt - j0);
        #pragma unroll 4
        for (int jj = 0; jj < nb; jj++) {
            int s = __shfl_sync(0xffffffffu, idx, jj);
            float4 v = ((const float4*)(g_h0 + (size_t)s * D))[lane];
            acc.x += v.x; acc.y += v.y; acc.z += v.z; acc.w += v.w;
        }
    }
    float inv = 1.f / fmaxf((float)cnt, 1.f);
    acc.x *= inv; acc.y *= inv; acc.z *= inv; acc.w *= inv;
    ((float4*)(g_agg + (size_t)warp * D))[lane] = acc;
    if (lane == 0) g_cnt[warp] = 0;   // restore all-zero invariant for next replay
}

// ---------------- K6: fused 3xBF16-split GEMM + LN + GELU + gate ----------------
#define GBM 128
#define PLN 5120                        // 128*40 ushorts per plane
#define SM_BYTES (128 * 132 * 4)        // C dump dominates (67584 B)

__global__ void __launch_bounds__(256) k_gemm_fused(
        const float* __restrict__ bl,
        const float* __restrict__ lnw, const float* __restrict__ lnb,
        const float* __restrict__ gate_w, const float* __restrict__ gate_b) {
    extern __shared__ float sm[];
    unsigned short* As_h = (unsigned short*)sm;
    unsigned short* As_l = As_h + PLN;
    unsigned short* Bs_h = As_h + 2 * PLN;
    unsigned short* Bs_l = As_h + 3 * PLN;
    float* Cs = sm;                     // alias post-mainloop

    const int tid  = threadIdx.x;
    const int lane = tid & 31, wid = tid >> 5;
    const int row0 = blockIdx.x * GBM;
    const int wm = wid >> 1, wn = wid & 1;
    const int g = lane >> 2, tig = lane & 3;

    const int arow = tid >> 1;
    const int akq  = (tid & 1) * 4;
    const int growA = row0 + arow;
    const bool aok = growA < N_NODES;

    const int bn  = tid >> 1;
    const int bkk = (tid & 1) * 16;

    float c[2][8][4];
    #pragma unroll
    for (int mt = 0; mt < 2; mt++)
        #pragma unroll
        for (int nt = 0; nt < 8; nt++)
            #pragma unroll
            for (int j = 0; j < 4; j++) c[mt][nt][j] = 0.f;

    for (int k0 = 0; k0 < 2 * D; k0 += 32) {
        {
            const bool lhs = (k0 < D);
            const float* srcrow = lhs ? (g_agg + (size_t)growA * D + k0)
                                      : (g_h0  + (size_t)growA * D + (k0 - D));
            #pragma unroll
            for (int i = 0; i < 4; i++) {
                float4 v = aok ? ((const float4*)srcrow)[akq + i]
                               : make_float4(0.f, 0.f, 0.f, 0.f);
                float f[4] = {v.x, v.y, v.z, v.w};
                unsigned short hu[4], lu[4];
                #pragma unroll
                for (int cmp = 0; cmp < 4; cmp++) {
                    hu[cmp] = bf16_of(f[cmp]);
                    lu[cmp] = bf16_of(f[cmp] - bf16_back(hu[cmp]));
                }
                int kl = (akq + i) * 4;
                unsigned h01 = (unsigned)hu[0] | ((unsigned)hu[1] << 16);
                unsigned h23 = (unsigned)hu[2] | ((unsigned)hu[3] << 16);
                unsigned l01 = (unsigned)lu[0] | ((unsigned)lu[1] << 16);
                unsigned l23 = (unsigned)lu[2] | ((unsigned)lu[3] << 16);
                *(uint2*)&As_h[arow * 40 + kl] = make_uint2(h01, h23);
                *(uint2*)&As_l[arow * 40 + kl] = make_uint2(l01, l23);
            }
        }
        {
            const unsigned short* sh = g_Bh + (size_t)bn * (2 * D) + k0 + bkk;
            const unsigned short* sl = g_Bl + (size_t)bn * (2 * D) + k0 + bkk;
            *(uint4*)&Bs_h[bn * 40 + bkk]     = *(const uint4*)sh;
            *(uint4*)&Bs_h[bn * 40 + bkk + 8] = *(const uint4*)(sh + 8);
            *(uint4*)&Bs_l[bn * 40 + bkk]     = *(const uint4*)sl;
            *(uint4*)&Bs_l[bn * 40 + bkk + 8] = *(const uint4*)(sl + 8);
        }
        __syncthreads();

        #pragma unroll
        for (int ks = 0; ks < 32; ks += 16) {
            int kbase = ks + tig * 2;
            unsigned ah[2][4], al[2][4];
            #pragma unroll
            for (int mt = 0; mt < 2; mt++) {
                int r = wm * 32 + mt * 16 + g;
                ah[mt][0] = *(unsigned*)&As_h[r * 40 + kbase];
                ah[mt][1] = *(unsigned*)&As_h[(r + 8) * 40 + kbase];
                ah[mt][2] = *(unsigned*)&As_h[r * 40 + kbase + 8];
                ah[mt][3] = *(unsigned*)&As_h[(r + 8) * 40 + kbase + 8];
                al[mt][0] = *(unsigned*)&As_l[r * 40 + kbase];
                al[mt][1] = *(unsigned*)&As_l[(r + 8) * 40 + kbase];
                al[mt][2] = *(unsigned*)&As_l[r * 40 + kbase + 8];
                al[mt][3] = *(unsigned*)&As_l[(r + 8) * 40 + kbase + 8];
            }
            unsigned bh[8][2], blo[8][2];
            #pragma unroll
            for (int nt = 0; nt < 8; nt++) {
                int n = wn * 64 + nt * 8 + g;
                bh[nt][0]  = *(unsigned*)&Bs_h[n * 40 + kbase];
                bh[nt][1]  = *(unsigned*)&Bs_h[n * 40 + kbase + 8];
                blo[nt][0] = *(unsigned*)&Bs_l[n * 40 + kbase];
                blo[nt][1] = *(unsigned*)&Bs_l[n * 40 + kbase + 8];
            }
            #pragma unroll
            for (int mt = 0; mt < 2; mt++)
                #pragma unroll
                for (int nt = 0; nt < 8; nt++) {
                    MMA_BF16(c[mt][nt], ah[mt], bh[nt]);
                    MMA_BF16(c[mt][nt], ah[mt], blo[nt]);
                    MMA_BF16(c[mt][nt], al[mt], bh[nt]);
                }
        }
        __syncthreads();
    }

    #pragma unroll
    for (int mt = 0; mt < 2; mt++)
        #pragma unroll
        for (int nt = 0; nt < 8; nt++) {
            int r  = wm * 32 + mt * 16 + g;
            int cc = wn * 64 + nt * 8 + 2 * tig;
            Cs[r * 132 + cc]           = c[mt][nt][0];
            Cs[r * 132 + cc + 1]       = c[mt][nt][1];
            Cs[(r + 8) * 132 + cc]     = c[mt][nt][2];
            Cs[(r + 8) * 132 + cc + 1] = c[mt][nt][3];
        }
    __syncthreads();

    float4 bl4 = ((const float4*)bl)[lane];
    float4 wv  = ((const float4*)lnw)[lane];
    float4 bv  = ((const float4*)lnb)[lane];
    float4 gw  = ((const float4*)gate_w)[lane];
    float gb = gate_b[0];
    #pragma unroll 1
    for (int i = 0; i < 16; i++) {
        int r = wid * 16 + i;
        int grow = row0 + r;
        if (grow >= N_NODES) break;
        float4 v = *(float4*)&Cs[r * 132 + lane * 4];
        v.x += bl4.x; v.y += bl4.y; v.z += bl4.z; v.w += bl4.w;
        float s = v.x + v.y + v.z + v.w;
        #pragma unroll
        for (int o = 16; o; o >>= 1) s += __shfl_xor_sync(0xffffffffu, s, o);
        float mu = s * (1.f / 128.f);
        float d0 = v.x - mu, d1 = v.y - mu, d2 = v.z - mu, d3 = v.w - mu;
        float q = d0 * d0 + d1 * d1 + d2 * d2 + d3 * d3;
        #pragma unroll
        for (int o = 16; o; o >>= 1) q += __shfl_xor_sync(0xffffffffu, q, o);
        float rstd = rsqrtf(q * (1.f / 128.f) + LN_EPS);
        float h0v = gelu_exact(d0 * rstd * wv.x + bv.x);
        float h1v = gelu_exact(d1 * rstd * wv.y + bv.y);
        float h2v = gelu_exact(d2 * rstd * wv.z + bv.z);
        float h3v = gelu_exact(d3 * rstd * wv.w + bv.w);
        float4 o4 = {h0v, h1v, h2v, h3v};
        ((float4*)(g_h1 + (size_t)grow * D))[lane] = o4;
        float p = h0v * gw.x + h1v * gw.y + h2v * gw.z + h3v * gw.w;
        #pragma unroll
        for (int o = 16; o; o >>= 1) p += __shfl_xor_sync(0xffffffffu, p, o);
        if (lane == 0) g_gate[grow] = p + gb;
    }
}

// ---------------- K7: softmax-pool + LN-384 head, merged (512 thr) ----------------
__device__ __forceinline__ int lower_bound_i(const int* a, int n, int v) {
    int lo = 0, hi = n;
    while (lo < hi) { int m = (lo + hi) >> 1; if (a[m] < v) lo = m + 1; else hi = m; }
    return lo;
}

__global__ void __launch_bounds__(512) k_pool_head(
        const int* __restrict__ batch,
        const float* __restrict__ mw, const float* __restrict__ mb,
        const float* __restrict__ fcW, const float* __restrict__ fcb,
        const float* __restrict__ gws,
        float* __restrict__ attn_out, float* __restrict__ gemb,
        float* __restrict__ logits) {
    __shared__ float red[512];
    __shared__ int s_lo, s_hi;
    int gidx = blockIdx.x, t = threadIdx.x;
    if (t == 0) {
        s_lo = lower_bound_i(batch, N_NODES, gidx);
        s_hi = lower_bound_i(batch, N_NODES, gidx + 1);
    }
    __syncthreads();
    int lo = s_lo, hi = s_hi;

    float m = -INFINITY;
    for (int i = lo + t; i < hi; i += 512) m = fmaxf(m, g_gate[i]);
    red[t] = m; __syncthreads();
    #pragma unroll
    for (int s = 256; s; s >>= 1) { if (t < s) red[t] = fmaxf(red[t], red[t + s]); __syncthreads(); }
    m = red[0]; __syncthreads();

    float sum = 0.f;
    for (int i = lo + t; i < hi; i += 512) sum += expf(g_gate[i] - m);
    red[t] = sum; __syncthreads();
    #pragma unroll
    for (int s = 256; s; s >>= 1) { if (t < s) red[t] += red[t + s]; __syncthreads(); }
    float denom = red[0]; __syncthreads();
    float inv = (denom > 0.f) ? 1.f / denom : 0.f;

    for (int i = lo + t; i < hi; i += 512) attn_out[i] = expf(g_gate[i] - m) * inv;
    __syncthreads();

    int col = t & 127, quart = t >> 7;
    int n = hi - lo;
    int rbeg = lo + (n * quart) / 4;
    int rend = lo + (n * (quart + 1)) / 4;
    float acc = 0.f;
    int i = rbeg;
    for (; i + 4 <= rend; i += 4) {
        float a0 = attn_out[i],     a1 = attn_out[i + 1];
        float a2 = attn_out[i + 2], a3 = attn_out[i + 3];
        float v0 = g_h1[(size_t)i * D + col];
        float v1 = g_h1[(size_t)(i + 1) * D + col];
        float v2 = g_h1[(size_t)(i + 2) * D + col];
        float v3 = g_h1[(size_t)(i + 3) * D + col];
        acc += a0 * v0 + a1 * v1 + a2 * v2 + a3 * v3;
    }
    for (; i < rend; i++) acc += attn_out[i] * g_h1[(size_t)i * D + col];
    red[t] = acc; __syncthreads();

    float ge = 0.f;
    if (t < 128) {
        ge = red[t] + red[t + 128] + red[t + 256] + red[t + 384];
        gemb[gidx * D + t] = ge;
    }
    __syncthreads();

    float e0 = 0.f, accm = 0.f, accf = 0.f;
    if (t < 128) {
        e0   = gws[0] * ge;
        accm = g_msg [(size_t)gidx * D + t];
        accf = g_feat[(size_t)gidx * D + t];
    }
    float s3 = (t < 128) ? (e0 + accm + accf) : 0.f;
    red[t] = s3; __syncthreads();
    #pragma unroll
    for (int ss = 256; ss; ss >>= 1) { if (t < ss) red[t] += red[t + ss]; __syncthreads(); }
    float mu = red[0] * (1.f / 384.f); __syncthreads();

    float qq = 0.f;
    float d0 = e0 - mu, d1 = accm - mu, d2 = accf - mu;
    if (t < 128) qq = d0 * d0 + d1 * d1 + d2 * d2;
    red[t] = qq; __syncthreads();
    #pragma unroll
    for (int ss = 256; ss; ss >>= 1) { if (t < ss) red[t] += red[t + ss]; __syncthreads(); }
    float rstd = rsqrtf(red[0] * (1.f / 384.f) + LN_EPS); __syncthreads();

    float p = 0.f;
    if (t < 128) {
        float n0 = d0 * rstd * mw[t]         + mb[t];
        float n1 = d1 * rstd * mw[D + t]     + mb[D + t];
        float n2 = d2 * rstd * mw[2 * D + t] + mb[2 * D + t];
        p = n0 * fcW[t] + n1 * fcW[D + t] + n2 * fcW[2 * D + t];
    }
    red[t] = p; __syncthreads();
    #pragma unroll
    for (int ss = 256; ss; ss >>= 1) { if (t < ss) red[t] += red[t + ss]; __syncthreads(); }
    if (t == 0) logits[gidx] = red[0] + fcb[0];
}

// ---------------- launch (fork/join; 3-kernel side chain) ----------------
extern "C" void kernel_launch(void* const* d_in, const int* in_sizes, int n_in,
                              void* d_out, int out_size) {
    (void)n_in; (void)out_size;
    const float* x          = (const float*)d_in[0];
    const int*   edge_index = (const int*)  d_in[1];
    const int*   batch      = (const int*)  d_in[2];
    int o = (in_sizes[3] == 1) ? 1 : 0;   // skip scalar batch_size slot if present
    const float* text     = (const float*)d_in[3 + o];
    const float* featm    = (const float*)d_in[4 + o];
    const float* ln_pw    = (const float*)d_in[5 + o];
    const float* ln_pb    = (const float*)d_in[6 + o];
    const float* W_l      = (const float*)d_in[7 + o];
    const float* b_l      = (const float*)d_in[8 + o];
    const float* W_r      = (const float*)d_in[9 + o];
    const float* ln_cw    = (const float*)d_in[10 + o];
    const float* ln_cb    = (const float*)d_in[11 + o];
    const float* gate_w   = (const float*)d_in[12 + o];
    const float* gate_b   = (const float*)d_in[13 + o];
    const float* gweight  = (const float*)d_in[14 + o];
    const float* msg_W    = (const float*)d_in[15 + o];
    const float* msg_b    = (const float*)d_in[16 + o];
    const float* feat_W   = (const float*)d_in[17 + o];
    const float* feat_b   = (const float*)d_in[18 + o];
    const float* mixed_w  = (const float*)d_in[19 + o];
    const float* mixed_b  = (const float*)d_in[20 + o];
    const float* fc1_W    = (const float*)d_in[21 + o];
    const float* fc1_b    = (const float*)d_in[22 + o];

    float* out     = (float*)d_out;
    float* logits  = out;                 // [512]
    float* gemb    = out + NG;            // [512,128]
    float* attn    = out + NG + NG * D;   // [50000]

    static cudaStream_t s2 = nullptr;
    static cudaEvent_t efork = nullptr, eln = nullptr, ejoin = nullptr;
    if (s2 == nullptr) {
        cudaStreamCreateWithFlags(&s2, cudaStreamNonBlocking);
        cudaEventCreateWithFlags(&efork, cudaEventDisableTiming);
        cudaEventCreateWithFlags(&eln,   cudaEventDisableTiming);
        cudaEventCreateWithFlags(&ejoin, cudaEventDisableTiming);
        cudaFuncSetAttribute(k_gemm_fused, cudaFuncAttributeMaxDynamicSharedMemorySize,
                             SM_BYTES);
    }

    // ---- fork: side stream handles edge pipeline (g_cnt arrives zeroed)
    cudaEventRecord(efork, 0);
    cudaStreamWaitEvent(s2, efork, 0);

    k_hist<<<(N_EDGES + 255) / 256, 256, 0, s2>>>(edge_index);
    k_scan<<<SCAN_BLOCKS, 1024, 0, s2>>>();
    k_edge_sort<<<(N_EDGES + 255) / 256, 256, 0, s2>>>(edge_index);

    // ---- main: node layernorm + B prep; signal h0 ready
    k_ln_project<<<(N_NODES + 7) / 8, 256>>>(x, ln_pw, ln_pb, W_l, W_r);
    cudaEventRecord(eln, 0);
    cudaStreamWaitEvent(s2, eln, 0);

    // ---- side: aggregate (needs edges + h0); main: msg/feat GEMVs (compute-light)
    k_aggregate<<<(N_NODES * 32 + 255) / 256, 256, 0, s2>>>();
    cudaEventRecord(ejoin, s2);
    k_msgfeat<<<NG / GPG, 128>>>(text, featm, msg_W, msg_b, feat_W, feat_b);

    // ---- join, then the dependent chain
    cudaStreamWaitEvent(0, ejoin, 0);
    k_gemm_fused<<<(N_NODES + GBM - 1) / GBM, 256, SM_BYTES>>>(
        b_l, ln_cw, ln_cb, gate_w, gate_b);
    k_pool_head<<<NG, 512>>>(batch, mixed_w, mixed_b, fc1_W, fc1_b, gweight,
                             attn, gemb, logits);
}

// round 16
// speedup vs baseline: 1.0294x; 1.0294x over previous
#include <cuda_runtime.h>
#include <cuda_bf16.h>
#include <math.h>
#include <stdint.h>

#define N_NODES 50000
#define N_EDGES 800000
#define NG      512
#define D       128
#define TXT     768
#define MAN     14
#define LN_EPS  1e-5f
#define SCAN_BLOCKS 49   // ceil(50000/1024)

// ---------------- scratch (device globals; no allocs allowed) ----------------
__device__ float g_h0 [N_NODES * D];   // layernorm(x)
__device__ float g_agg[N_NODES * D];   // neighbor MEAN
__device__ float g_h1 [N_NODES * D];   // h2 = gelu(LN(GEMM out))
__device__ float g_gate[N_NODES];      // gate logits
__device__ int   g_cnt[N_NODES];       // in-degree histogram (zero-init; self-resetting)
__device__ int   g_off[N_NODES];       // exclusive scan (bucket start)
__device__ int   g_cursor[N_NODES];    // scatter cursor
__device__ int   g_aggv[64];           // scan block sums
__device__ int   g_scan_ctr;           // publish counter (zero-init; reset by edge_sort)
__device__ int   g_ssrc[N_EDGES];      // src sorted by dst
__device__ float g_msg [NG * D];       // precomputed gelu(text@msgW+b)
__device__ float g_feat[NG * D];       // precomputed gelu(feat@featW+b)
// bf16 split planes of [Wl;Wr], TRANSPOSED: [n][k] with k contiguous (256 per n)
__device__ unsigned short g_Bh[D * 2 * D];
__device__ unsigned short g_Bl[D * 2 * D];

__device__ __forceinline__ float gelu_exact(float x) {
    return 0.5f * x * (1.0f + erff(x * 0.70710678118654752440f));
}

__device__ __forceinline__ unsigned short bf16_of(float x) {
    __nv_bfloat16 h = __float2bfloat16_rn(x);
    return *(unsigned short*)&h;
}
__device__ __forceinline__ float bf16_back(unsigned short u) {
    __nv_bfloat16 h = *(__nv_bfloat16*)&u;
    return __bfloat162float(h);
}

#define MMA_BF16(c, a, b)                                                     \
    asm volatile("mma.sync.aligned.m16n8k16.row.col.f32.bf16.bf16.f32 "       \
                 "{%0,%1,%2,%3}, {%4,%5,%6,%7}, {%8,%9}, {%0,%1,%2,%3};"      \
                 : "+f"((c)[0]), "+f"((c)[1]), "+f"((c)[2]), "+f"((c)[3])     \
                 : "r"((a)[0]), "r"((a)[1]), "r"((a)[2]), "r"((a)[3]),        \
                   "r"((b)[0]), "r"((b)[1]))

// ---------------- main K1: h0 = layernorm(x); prep B bf16 planes ----------------
__global__ void k_ln_project(const float* __restrict__ x,
                             const float* __restrict__ w,
                             const float* __restrict__ b,
                             const float* __restrict__ Wl,
                             const float* __restrict__ Wr) {
    int gt = blockIdx.x * blockDim.x + threadIdx.x;
    if (gt < 2 * D * D) {
        int kg = gt >> 7, n = gt & 127;
        float v = (kg < D) ? Wl[(size_t)kg * D + n] : Wr[(size_t)(kg - D) * D + n];
        unsigned short hi = bf16_of(v);
        unsigned short lo = bf16_of(v - bf16_back(hi));
        g_Bh[n * 2 * D + kg] = hi;
        g_Bl[n * 2 * D + kg] = lo;
    }
    int warp = gt >> 5;
    int lane = threadIdx.x & 31;
    if (warp >= N_NODES) return;
    float4 v = ((const float4*)(x + (size_t)warp * D))[lane];
    float s = v.x + v.y + v.z + v.w;
    #pragma unroll
    for (int o = 16; o; o >>= 1) s += __shfl_xor_sync(0xffffffffu, s, o);
    float mu = s * (1.f / 128.f);
    float d0 = v.x - mu, d1 = v.y - mu, d2 = v.z - mu, d3 = v.w - mu;
    float q = d0 * d0 + d1 * d1 + d2 * d2 + d3 * d3;
    #pragma unroll
    for (int o = 16; o; o >>= 1) q += __shfl_xor_sync(0xffffffffu, q, o);
    float rstd = rsqrtf(q * (1.f / 128.f) + LN_EPS);
    float4 wv = ((const float4*)w)[lane];
    float4 bv = ((const float4*)b)[lane];
    float4 o4;
    o4.x = d0 * rstd * wv.x + bv.x;
    o4.y = d1 * rstd * wv.y + bv.y;
    o4.z = d2 * rstd * wv.z + bv.z;
    o4.w = d3 * rstd * wv.w + bv.w;
    ((float4*)(g_h0 + (size_t)warp * D))[lane] = o4;
}

// ---------------- side K2: histogram of dst (g_cnt arrives zeroed) ----------------
__global__ void k_hist(const int* __restrict__ ei) {
    int e = blockIdx.x * blockDim.x + threadIdx.x;
    if (e < N_EDGES) atomicAdd(&g_cnt[ei[N_EDGES + e]], 1);
}

// ---------------- side K3: single-pass scan (publish + spin + warp lookback) ----------------
__global__ void k_scan() {
    __shared__ int s[1024];
    __shared__ int s_prev;
    int t = threadIdx.x, b = blockIdx.x;
    int i = b * 1024 + t;
    int v = (i < N_NODES) ? g_cnt[i] : 0;
    s[t] = v; __syncthreads();
    #pragma unroll
    for (int off = 1; off < 1024; off <<= 1) {
        int a = (t >= off) ? s[t - off] : 0;
        __syncthreads();
        s[t] += a; __syncthreads();
    }
    if (t == 0) {
        g_aggv[b] = s[1023];
        __threadfence();
        atomicAdd(&g_scan_ctr, 1);
        while (atomicAdd(&g_scan_ctr, 0) < SCAN_BLOCKS) { }
    }
    __syncthreads();
    if (t < 32) {
        int v1 = (t < b)      ? *((volatile int*)&g_aggv[t])      : 0;
        int v2 = (t + 32 < b) ? *((volatile int*)&g_aggv[t + 32]) : 0;
        int p = v1 + v2;
        #pragma unroll
        for (int o = 16; o; o >>= 1) p += __shfl_xor_sync(0xffffffffu, p, o);
        if (t == 0) s_prev = p;
    }
    __syncthreads();
    if (i < N_NODES) {
        int o = s[t] - v + s_prev;
        g_off[i] = o;
        g_cursor[i] = o;
    }
}

// ---------------- side K4: scatter src into dst-sorted order; reset scan ctr ----------------
__global__ void k_edge_sort(const int* __restrict__ ei) {
    if (blockIdx.x == 0 && threadIdx.x == 0) g_scan_ctr = 0;   // stream-ordered after k_scan
    int e = blockIdx.x * blockDim.x + threadIdx.x;
    if (e >= N_EDGES) return;
    int src = ei[e];
    int dst = ei[N_EDGES + e];
    int pos = atomicAdd(&g_cursor[dst], 1);
    g_ssrc[pos] = src;
}

// ---------------- main K1b: msg/feat GEMVs ----------------
#define GPG 8
__global__ void __launch_bounds__(128) k_msgfeat(const float* __restrict__ text,
                                                 const float* __restrict__ featm,
                                                 const float* __restrict__ msgW,
                                                 const float* __restrict__ msgb,
                                                 const float* __restrict__ featW,
                                                 const float* __restrict__ featb) {
    __shared__ float ts[GPG][TXT];
    __shared__ float fs[GPG][MAN];
    int g0 = blockIdx.x * GPG, t = threadIdx.x;

    for (int i = t; i < GPG * TXT; i += 128) {
        int q = i / TXT, k = i % TXT;
        ts[q][k] = text[(size_t)(g0 + q) * TXT + k];
    }
    for (int i = t; i < GPG * MAN; i += 128) {
        int q = i / MAN, k = i % MAN;
        fs[q][k] = featm[(size_t)(g0 + q) * MAN + k];
    }
    __syncthreads();

    float accm[GPG];
    #pragma unroll
    for (int q = 0; q < GPG; q++) accm[q] = 0.f;
    #pragma unroll 4
    for (int k = 0; k < TXT; k++) {
        float w = msgW[(size_t)k * D + t];
        #pragma unroll
        for (int q = 0; q < GPG; q++) accm[q] += ts[q][k] * w;
    }
    float mbv = msgb[t];
    #pragma unroll
    for (int q = 0; q < GPG; q++)
        g_msg[(size_t)(g0 + q) * D + t] = gelu_exact(accm[q] + mbv);

    float accf[GPG];
    #pragma unroll
    for (int q = 0; q < GPG; q++) accf[q] = 0.f;
    #pragma unroll
    for (int k = 0; k < MAN; k++) {
        float w = featW[(size_t)k * D + t];
        #pragma unroll
        for (int q = 0; q < GPG; q++) accf[q] += fs[q][k] * w;
    }
    float fbv = featb[t];
    #pragma unroll
    for (int q = 0; q < GPG; q++)
        g_feat[(size_t)(g0 + q) * D + t] = gelu_exact(accf[q] + fbv);
}

// ---------------- side K5: per-node mean aggregation, 2 warps per node ----------------
// sub-warp 0 sums first half of the neighbor list, sub-warp 1 the second half;
// partials combined via smem. Doubles rows in flight, halves serial depth.
__global__ void __launch_bounds__(256) k_aggregate() {
    __shared__ float4 sacc[4][32];
    int gw   = (blockIdx.x * blockDim.x + threadIdx.x) >> 5;
    int lane = threadIdx.x & 31;
    int node = gw >> 1;
    int sub  = gw & 1;
    int pair = (threadIdx.x >> 5) >> 1;   // 0..3 within block
    // grid sized exactly: 2*N_NODES warps, no bounds check needed

    int start = g_off[node];
    int cnt   = g_cnt[node];
    int half  = (cnt + 1) >> 1;
    int mybeg = sub ? half : 0;
    int myend = sub ? cnt  : half;

    float4 acc = make_float4(0.f, 0.f, 0.f, 0.f);
    for (int j0 = mybeg; j0 < myend; j0 += 32) {
        int idx = (j0 + lane < myend) ? g_ssrc[start + j0 + lane] : 0;
        int nb = min(32, myend - j0);
        #pragma unroll 4
        for (int jj = 0; jj < nb; jj++) {
            int s = __shfl_sync(0xffffffffu, idx, jj);
            float4 v = ((const float4*)(g_h0 + (size_t)s * D))[lane];
            acc.x += v.x; acc.y += v.y; acc.z += v.z; acc.w += v.w;
        }
    }
    if (sub == 0) {
        sacc[pair][lane] = acc;
        if (lane == 0) g_cnt[node] = 0;   // restore all-zero invariant
    }
    __syncthreads();
    if (sub == 1) {
        float4 o = sacc[pair][lane];
        float inv = 1.f / fmaxf((float)cnt, 1.f);
        o.x = (o.x + acc.x) * inv;
        o.y = (o.y + acc.y) * inv;
        o.z = (o.z + acc.z) * inv;
        o.w = (o.w + acc.w) * inv;
        ((float4*)(g_agg + (size_t)node * D))[lane] = o;
    }
}

// ---------------- K6: fused 3xBF16-split GEMM + LN + GELU + gate ----------------
#define GBM 128
#define PLN 5120                        // 128*40 ushorts per plane
#define SM_BYTES (128 * 132 * 4)        // C dump dominates (67584 B)

__global__ void __launch_bounds__(256) k_gemm_fused(
        const float* __restrict__ bl,
        const float* __restrict__ lnw, const float* __restrict__ lnb,
        const float* __restrict__ gate_w, const float* __restrict__ gate_b) {
    extern __shared__ float sm[];
    unsigned short* As_h = (unsigned short*)sm;
    unsigned short* As_l = As_h + PLN;
    unsigned short* Bs_h = As_h + 2 * PLN;
    unsigned short* Bs_l = As_h + 3 * PLN;
    float* Cs = sm;                     // alias post-mainloop

    const int tid  = threadIdx.x;
    const int lane = tid & 31, wid = tid >> 5;
    const int row0 = blockIdx.x * GBM;
    const int wm = wid >> 1, wn = wid & 1;
    const int g = lane >> 2, tig = lane & 3;

    const int arow = tid >> 1;
    const int akq  = (tid & 1) * 4;
    const int growA = row0 + arow;
    const bool aok = growA < N_NODES;

    const int bn  = tid >> 1;
    const int bkk = (tid & 1) * 16;

    float c[2][8][4];
    #pragma unroll
    for (int mt = 0; mt < 2; mt++)
        #pragma unroll
        for (int nt = 0; nt < 8; nt++)
            #pragma unroll
            for (int j = 0; j < 4; j++) c[mt][nt][j] = 0.f;

    for (int k0 = 0; k0 < 2 * D; k0 += 32) {
        {
            const bool lhs = (k0 < D);
            const float* srcrow = lhs ? (g_agg + (size_t)growA * D + k0)
                                      : (g_h0  + (size_t)growA * D + (k0 - D));
            #pragma unroll
            for (int i = 0; i < 4; i++) {
                float4 v = aok ? ((const float4*)srcrow)[akq + i]
                               : make_float4(0.f, 0.f, 0.f, 0.f);
                float f[4] = {v.x, v.y, v.z, v.w};
                unsigned short hu[4], lu[4];
                #pragma unroll
                for (int cmp = 0; cmp < 4; cmp++) {
                    hu[cmp] = bf16_of(f[cmp]);
                    lu[cmp] = bf16_of(f[cmp] - bf16_back(hu[cmp]));
                }
                int kl = (akq + i) * 4;
                unsigned h01 = (unsigned)hu[0] | ((unsigned)hu[1] << 16);
                unsigned h23 = (unsigned)hu[2] | ((unsigned)hu[3] << 16);
                unsigned l01 = (unsigned)lu[0] | ((unsigned)lu[1] << 16);
                unsigned l23 = (unsigned)lu[2] | ((unsigned)lu[3] << 16);
                *(uint2*)&As_h[arow * 40 + kl] = make_uint2(h01, h23);
                *(uint2*)&As_l[arow * 40 + kl] = make_uint2(l01, l23);
            }
        }
        {
            const unsigned short* sh = g_Bh + (size_t)bn * (2 * D) + k0 + bkk;
            const unsigned short* sl = g_Bl + (size_t)bn * (2 * D) + k0 + bkk;
            *(uint4*)&Bs_h[bn * 40 + bkk]     = *(const uint4*)sh;
            *(uint4*)&Bs_h[bn * 40 + bkk + 8] = *(const uint4*)(sh + 8);
            *(uint4*)&Bs_l[bn * 40 + bkk]     = *(const uint4*)sl;
            *(uint4*)&Bs_l[bn * 40 + bkk + 8] = *(const uint4*)(sl + 8);
        }
        __syncthreads();

        #pragma unroll
        for (int ks = 0; ks < 32; ks += 16) {
            int kbase = ks + tig * 2;
            unsigned ah[2][4], al[2][4];
            #pragma unroll
            for (int mt = 0; mt < 2; mt++) {
                int r = wm * 32 + mt * 16 + g;
                ah[mt][0] = *(unsigned*)&As_h[r * 40 + kbase];
                ah[mt][1] = *(unsigned*)&As_h[(r + 8) * 40 + kbase];
                ah[mt][2] = *(unsigned*)&As_h[r * 40 + kbase + 8];
                ah[mt][3] = *(unsigned*)&As_h[(r + 8) * 40 + kbase + 8];
                al[mt][0] = *(unsigned*)&As_l[r * 40 + kbase];
                al[mt][1] = *(unsigned*)&As_l[(r + 8) * 40 + kbase];
                al[mt][2] = *(unsigned*)&As_l[r * 40 + kbase + 8];
                al[mt][3] = *(unsigned*)&As_l[(r + 8) * 40 + kbase + 8];
            }
            unsigned bh[8][2], blo[8][2];
            #pragma unroll
            for (int nt = 0; nt < 8; nt++) {
                int n = wn * 64 + nt * 8 + g;
                bh[nt][0]  = *(unsigned*)&Bs_h[n * 40 + kbase];
                bh[nt][1]  = *(unsigned*)&Bs_h[n * 40 + kbase + 8];
                blo[nt][0] = *(unsigned*)&Bs_l[n * 40 + kbase];
                blo[nt][1] = *(unsigned*)&Bs_l[n * 40 + kbase + 8];
            }
            #pragma unroll
            for (int mt = 0; mt < 2; mt++)
                #pragma unroll
                for (int nt = 0; nt < 8; nt++) {
                    MMA_BF16(c[mt][nt], ah[mt], bh[nt]);
                    MMA_BF16(c[mt][nt], ah[mt], blo[nt]);
                    MMA_BF16(c[mt][nt], al[mt], bh[nt]);
                }
        }
        __syncthreads();
    }

    #pragma unroll
    for (int mt = 0; mt < 2; mt++)
        #pragma unroll
        for (int nt = 0; nt < 8; nt++) {
            int r  = wm * 32 + mt * 16 + g;
            int cc = wn * 64 + nt * 8 + 2 * tig;
            Cs[r * 132 + cc]           = c[mt][nt][0];
            Cs[r * 132 + cc + 1]       = c[mt][nt][1];
            Cs[(r + 8) * 132 + cc]     = c[mt][nt][2];
            Cs[(r + 8) * 132 + cc + 1] = c[mt][nt][3];
        }
    __syncthreads();

    float4 bl4 = ((const float4*)bl)[lane];
    float4 wv  = ((const float4*)lnw)[lane];
    float4 bv  = ((const float4*)lnb)[lane];
    float4 gw  = ((const float4*)gate_w)[lane];
    float gb = gate_b[0];
    #pragma unroll 1
    for (int i = 0; i < 16; i++) {
        int r = wid * 16 + i;
        int grow = row0 + r;
        if (grow >= N_NODES) break;
        float4 v = *(float4*)&Cs[r * 132 + lane * 4];
        v.x += bl4.x; v.y += bl4.y; v.z += bl4.z; v.w += bl4.w;
        float s = v.x + v.y + v.z + v.w;
        #pragma unroll
        for (int o = 16; o; o >>= 1) s += __shfl_xor_sync(0xffffffffu, s, o);
        float mu = s * (1.f / 128.f);
        float d0 = v.x - mu, d1 = v.y - mu, d2 = v.z - mu, d3 = v.w - mu;
        float q = d0 * d0 + d1 * d1 + d2 * d2 + d3 * d3;
        #pragma unroll
        for (int o = 16; o; o >>= 1) q += __shfl_xor_sync(0xffffffffu, q, o);
        float rstd = rsqrtf(q * (1.f / 128.f) + LN_EPS);
        float h0v = gelu_exact(d0 * rstd * wv.x + bv.x);
        float h1v = gelu_exact(d1 * rstd * wv.y + bv.y);
        float h2v = gelu_exact(d2 * rstd * wv.z + bv.z);
        float h3v = gelu_exact(d3 * rstd * wv.w + bv.w);
        float4 o4 = {h0v, h1v, h2v, h3v};
        ((float4*)(g_h1 + (size_t)grow * D))[lane] = o4;
        float p = h0v * gw.x + h1v * gw.y + h2v * gw.z + h3v * gw.w;
        #pragma unroll
        for (int o = 16; o; o >>= 1) p += __shfl_xor_sync(0xffffffffu, p, o);
        if (lane == 0) g_gate[grow] = p + gb;
    }
}

// ---------------- K7: softmax-pool + LN-384 head, merged (512 thr) ----------------
__device__ __forceinline__ int lower_bound_i(const int* a, int n, int v) {
    int lo = 0, hi = n;
    while (lo < hi) { int m = (lo + hi) >> 1; if (a[m] < v) lo = m + 1; else hi = m; }
    return lo;
}

__global__ void __launch_bounds__(512) k_pool_head(
        const int* __restrict__ batch,
        const float* __restrict__ mw, const float* __restrict__ mb,
        const float* __restrict__ fcW, const float* __restrict__ fcb,
        const float* __restrict__ gws,
        float* __restrict__ attn_out, float* __restrict__ gemb,
        float* __restrict__ logits) {
    __shared__ float red[512];
    __shared__ int s_lo, s_hi;
    int gidx = blockIdx.x, t = threadIdx.x;
    if (t == 0) {
        s_lo = lower_bound_i(batch, N_NODES, gidx);
        s_hi = lower_bound_i(batch, N_NODES, gidx + 1);
    }
    __syncthreads();
    int lo = s_lo, hi = s_hi;

    float m = -INFINITY;
    for (int i = lo + t; i < hi; i += 512) m = fmaxf(m, g_gate[i]);
    red[t] = m; __syncthreads();
    #pragma unroll
    for (int s = 256; s; s >>= 1) { if (t < s) red[t] = fmaxf(red[t], red[t + s]); __syncthreads(); }
    m = red[0]; __syncthreads();

    float sum = 0.f;
    for (int i = lo + t; i < hi; i += 512) sum += expf(g_gate[i] - m);
    red[t] = sum; __syncthreads();
    #pragma unroll
    for (int s = 256; s; s >>= 1) { if (t < s) red[t] += red[t + s]; __syncthreads(); }
    float denom = red[0]; __syncthreads();
    float inv = (denom > 0.f) ? 1.f / denom : 0.f;

    for (int i = lo + t; i < hi; i += 512) attn_out[i] = expf(g_gate[i] - m) * inv;
    __syncthreads();

    int col = t & 127, quart = t >> 7;
    int n = hi - lo;
    int rbeg = lo + (n * quart) / 4;
    int rend = lo + (n * (quart + 1)) / 4;
    float acc = 0.f;
    int i = rbeg;
    for (; i + 4 <= rend; i += 4) {
        float a0 = attn_out[i],     a1 = attn_out[i + 1];
        float a2 = attn_out[i + 2], a3 = attn_out[i + 3];
        float v0 = g_h1[(size_t)i * D + col];
        float v1 = g_h1[(size_t)(i + 1) * D + col];
        float v2 = g_h1[(size_t)(i + 2) * D + col];
        float v3 = g_h1[(size_t)(i + 3) * D + col];
        acc += a0 * v0 + a1 * v1 + a2 * v2 + a3 * v3;
    }
    for (; i < rend; i++) acc += attn_out[i] * g_h1[(size_t)i * D + col];
    red[t] = acc; __syncthreads();

    float ge = 0.f;
    if (t < 128) {
        ge = red[t] + red[t + 128] + red[t + 256] + red[t + 384];
        gemb[gidx * D + t] = ge;
    }
    __syncthreads();

    float e0 = 0.f, accm = 0.f, accf = 0.f;
    if (t < 128) {
        e0   = gws[0] * ge;
        accm = g_msg [(size_t)gidx * D + t];
        accf = g_feat[(size_t)gidx * D + t];
    }
    float s3 = (t < 128) ? (e0 + accm + accf) : 0.f;
    red[t] = s3; __syncthreads();
    #pragma unroll
    for (int ss = 256; ss; ss >>= 1) { if (t < ss) red[t] += red[t + ss]; __syncthreads(); }
    float mu = red[0] * (1.f / 384.f); __syncthreads();

    float qq = 0.f;
    float d0 = e0 - mu, d1 = accm - mu, d2 = accf - mu;
    if (t < 128) qq = d0 * d0 + d1 * d1 + d2 * d2;
    red[t] = qq; __syncthreads();
    #pragma unroll
    for (int ss = 256; ss; ss >>= 1) { if (t < ss) red[t] += red[t + ss]; __syncthreads(); }
    float rstd = rsqrtf(red[0] * (1.f / 384.f) + LN_EPS); __syncthreads();

    float p = 0.f;
    if (t < 128) {
        float n0 = d0 * rstd * mw[t]         + mb[t];
        float n1 = d1 * rstd * mw[D + t]     + mb[D + t];
        float n2 = d2 * rstd * mw[2 * D + t] + mb[2 * D + t];
        p = n0 * fcW[t] + n1 * fcW[D + t] + n2 * fcW[2 * D + t];
    }
    red[t] = p; __syncthreads();
    #pragma unroll
    for (int ss = 256; ss; ss >>= 1) { if (t < ss) red[t] += red[t + ss]; __syncthreads(); }
    if (t == 0) logits[gidx] = red[0] + fcb[0];
}

// ---------------- launch (fork/join; 3-kernel side chain) ----------------
extern "C" void kernel_launch(void* const* d_in, const int* in_sizes, int n_in,
                              void* d_out, int out_size) {
    (void)n_in; (void)out_size;
    const float* x          = (const float*)d_in[0];
    const int*   edge_index = (const int*)  d_in[1];
    const int*   batch      = (const int*)  d_in[2];
    int o = (in_sizes[3] == 1) ? 1 : 0;   // skip scalar batch_size slot if present
    const float* text     = (const float*)d_in[3 + o];
    const float* featm    = (const float*)d_in[4 + o];
    const float* ln_pw    = (const float*)d_in[5 + o];
    const float* ln_pb    = (const float*)d_in[6 + o];
    const float* W_l      = (const float*)d_in[7 + o];
    const float* b_l      = (const float*)d_in[8 + o];
    const float* W_r      = (const float*)d_in[9 + o];
    const float* ln_cw    = (const float*)d_in[10 + o];
    const float* ln_cb    = (const float*)d_in[11 + o];
    const float* gate_w   = (const float*)d_in[12 + o];
    const float* gate_b   = (const float*)d_in[13 + o];
    const float* gweight  = (const float*)d_in[14 + o];
    const float* msg_W    = (const float*)d_in[15 + o];
    const float* msg_b    = (const float*)d_in[16 + o];
    const float* feat_W   = (const float*)d_in[17 + o];
    const float* feat_b   = (const float*)d_in[18 + o];
    const float* mixed_w  = (const float*)d_in[19 + o];
    const float* mixed_b  = (const float*)d_in[20 + o];
    const float* fc1_W    = (const float*)d_in[21 + o];
    const float* fc1_b    = (const float*)d_in[22 + o];

    float* out     = (float*)d_out;
    float* logits  = out;                 // [512]
    float* gemb    = out + NG;            // [512,128]
    float* attn    = out + NG + NG * D;   // [50000]

    static cudaStream_t s2 = nullptr;
    static cudaEvent_t efork = nullptr, eln = nullptr, ejoin = nullptr;
    if (s2 == nullptr) {
        cudaStreamCreateWithFlags(&s2, cudaStreamNonBlocking);
        cudaEventCreateWithFlags(&efork, cudaEventDisableTiming);
        cudaEventCreateWithFlags(&eln,   cudaEventDisableTiming);
        cudaEventCreateWithFlags(&ejoin, cudaEventDisableTiming);
        cudaFuncSetAttribute(k_gemm_fused, cudaFuncAttributeMaxDynamicSharedMemorySize,
                             SM_BYTES);
    }

    // ---- fork: side stream handles edge pipeline (g_cnt arrives zeroed)
    cudaEventRecord(efork, 0);
    cudaStreamWaitEvent(s2, efork, 0);

    k_hist<<<(N_EDGES + 255) / 256, 256, 0, s2>>>(edge_index);
    k_scan<<<SCAN_BLOCKS, 1024, 0, s2>>>();
    k_edge_sort<<<(N_EDGES + 255) / 256, 256, 0, s2>>>(edge_index);

    // ---- main: node layernorm + B prep; signal h0 ready
    k_ln_project<<<(N_NODES + 7) / 8, 256>>>(x, ln_pw, ln_pb, W_l, W_r);
    cudaEventRecord(eln, 0);
    cudaStreamWaitEvent(s2, eln, 0);

    // ---- side: aggregate (needs edges + h0); main: msg/feat GEMVs (compute-light)
    k_aggregate<<<(N_NODES * 64) / 256, 256, 0, s2>>>();
    cudaEventRecord(ejoin, s2);
    k_msgfeat<<<NG / GPG, 128>>>(text, featm, msg_W, msg_b, feat_W, feat_b);

    // ---- join, then the dependent chain
    cudaStreamWaitEvent(0, ejoin, 0);
    k_gemm_fused<<<(N_NODES + GBM - 1) / GBM, 256, SM_BYTES>>>(
        b_l, ln_cw, ln_cb, gate_w, gate_b);
    k_pool_head<<<NG, 512>>>(batch, mixed_w, mixed_b, fc1_W, fc1_b, gweight,
                             attn, gemb, logits);
}